// round 1
// baseline (speedup 1.0000x reference)
#include <cuda_runtime.h>
#include <cstdint>

// Problem dims
#define NB   32
#define CIN  256
#define HW   32
#define OC   256
#define LSP  1024            // 32*32 spatial
#define KDIM 2304            // 256*9
#define NSUB 9
#define SUBSZ 256
#define NX   (NB*CIN*HW*HW)  // 8388608
#define NW   (OC*KDIM)       // 589824
#define NOUT (NB*OC*LSP)     // 8388608

// Scratch (device globals: allocation-free per harness rules)
__device__ unsigned g_maxbits[2];         // [0]=max|x| bits, [1]=max|w| bits
__device__ float    g_aq[NX];             // quantized activations (integers as f32)
__device__ float    g_wq[KDIM * OC];      // quantized weights, transposed [k][o]

// ---------------------------------------------------------------------------
__global__ void init_kernel() { g_maxbits[0] = 0u; g_maxbits[1] = 0u; }

__global__ void absmax_kernel(const float* __restrict__ p, int n, int slot) {
    float m = 0.f;
    for (int i = blockIdx.x * blockDim.x + threadIdx.x; i < n;
         i += gridDim.x * blockDim.x)
        m = fmaxf(m, fabsf(p[i]));
    #pragma unroll
    for (int o = 16; o; o >>= 1) m = fmaxf(m, __shfl_xor_sync(~0u, m, o));
    __shared__ float sm[32];
    int lane = threadIdx.x & 31, w = threadIdx.x >> 5;
    if (lane == 0) sm[w] = m;
    __syncthreads();
    if (w == 0) {
        m = (lane < (int)(blockDim.x >> 5)) ? sm[lane] : 0.f;
        #pragma unroll
        for (int o = 16; o; o >>= 1) m = fmaxf(m, __shfl_xor_sync(~0u, m, o));
        if (lane == 0) atomicMax(&g_maxbits[slot], __float_as_uint(m));
    }
}

// qa_int = rint(x / s * 255)  (exact integer in [-255,255], stored as f32)
__global__ void quant_act_kernel(const float* __restrict__ x) {
    float s = __uint_as_float(g_maxbits[0]) + 1e-12f;
    int i = blockIdx.x * blockDim.x + threadIdx.x;
    if (i < NX) g_aq[i] = rintf(x[i] / s * 255.f);
}

// qw_int = rint(w / s * 15), transposed to [k][o] for coalesced B-tile loads
__global__ void quant_w_kernel(const float* __restrict__ w) {
    float s = __uint_as_float(g_maxbits[1]) + 1e-12f;
    int i = blockIdx.x * blockDim.x + threadIdx.x;
    if (i < NW) {
        int o = i / KDIM, k = i - o * KDIM;
        g_wq[k * OC + o] = rintf(w[i] / s * 15.f);
    }
}

// ---------------------------------------------------------------------------
// packed 2-wide fp32 FMA (Blackwell f32x2) helpers
__device__ __forceinline__ void fma2(unsigned long long& acc,
                                     unsigned long long a,
                                     unsigned long long b) {
    asm("fma.rn.f32x2 %0, %1, %2, %0;" : "+l"(acc) : "l"(a), "l"(b));
}
__device__ __forceinline__ unsigned long long pack2(float lo, float hi) {
    unsigned long long r;
    asm("mov.b64 %0, {%1, %2};" : "=l"(r) : "f"(lo), "f"(hi));
    return r;
}
__device__ __forceinline__ void unpack2(unsigned long long v, float& lo, float& hi) {
    asm("mov.b64 {%0, %1}, %2;" : "=f"(lo), "=f"(hi) : "l"(v));
}

__device__ __forceinline__ float adc_q(float I) {
    float q = rintf(I / 0.001f);          // matches jnp.round(I / ADC_STEP)
    q = fminf(fmaxf(q, -128.f), 127.f);   // clip to [-2^7, 2^7-1]
    return q * 0.001f;
}

// ---------------------------------------------------------------------------
// Implicit GEMM: out[m, n] = sum_g ADC(C * sum_{i in group g} A[m,i] * W[n,i])
//   m = b*1024 + y*32 + x,  i = c*9 + ky*3 + kx
// BM=64, BN=64, KC=32, 256 threads, each thread -> 4x4 outputs.
#define BM 64
#define BN 64
#define KC 32

__global__ __launch_bounds__(256)
void conv_main_kernel(float* __restrict__ out) {
    __shared__ float As[KC][BM];
    __shared__ float Bs[KC][BN];

    const int m0 = blockIdx.x * BM;     // gridDim.x = 512
    const int n0 = blockIdx.y * BN;     // gridDim.y = 4
    const int t  = threadIdx.x;
    const int tm0 = (t >> 4) << 2;      // 0..60
    const int tn0 = (t & 15) << 2;      // 0..60

    const float sa = __uint_as_float(g_maxbits[0]) + 1e-12f;
    const float sw = __uint_as_float(g_maxbits[1]) + 1e-12f;
    const float C = (float)((double)sa / 255.0 * 0.125 *
                            (double)sw / 15.0 * (0.999 / 15.0));

    // A-load geometry (fixed per thread): column mm, rows (t>>6)+4j
    const int mm = t & 63;
    const int m  = m0 + mm;
    const int b  = m >> 10;
    const int l  = m & 1023;
    const int ycoord = l >> 5;
    const int xcoord = l & 31;
    const int abase  = b * (CIN * LSP);
    const int klbase = t >> 6;          // 0..3
    const int nnB    = t & 63;          // B-load column
    const int klbaseB = t >> 6;

    unsigned long long acc[4][2];
    float tot[4][4];
    #pragma unroll
    for (int i = 0; i < 4; i++) {
        acc[i][0] = 0ULL; acc[i][1] = 0ULL;
        #pragma unroll
        for (int j = 0; j < 4; j++) tot[i][j] = 0.f;
    }

    for (int g = 0; g < NSUB; g++) {
        for (int cc = 0; cc < SUBSZ / KC; cc++) {   // 8 chunks per group
            const int i0 = g * SUBSZ + cc * KC;
            __syncthreads();
            // ---- load A tile (gather with padding) ----
            #pragma unroll
            for (int j = 0; j < 8; j++) {
                int kl = klbase + j * 4;
                int i  = i0 + kl;
                unsigned c  = (unsigned)i / 9u;
                unsigned kk = (unsigned)i - 9u * c;
                int ky = (int)kk / 3;
                int kx = (int)kk - 3 * ky;
                int yy = ycoord + ky - 1;
                int xx = xcoord + kx - 1;
                float v = 0.f;
                if ((unsigned)yy < 32u && (unsigned)xx < 32u)
                    v = g_aq[abase + ((int)c * 32 + yy) * 32 + xx];
                As[kl][mm] = v;
            }
            // ---- load B tile (coalesced) ----
            #pragma unroll
            for (int j = 0; j < 8; j++) {
                int kl = klbaseB + j * 4;
                Bs[kl][nnB] = g_wq[(i0 + kl) * OC + n0 + nnB];
            }
            __syncthreads();
            // ---- compute ----
            #pragma unroll
            for (int kk = 0; kk < KC; kk++) {
                float4 a = *(const float4*)&As[kk][tm0];
                const ulonglong2 bv = *(const ulonglong2*)&Bs[kk][tn0];
                unsigned long long a0 = pack2(a.x, a.x);
                unsigned long long a1 = pack2(a.y, a.y);
                unsigned long long a2 = pack2(a.z, a.z);
                unsigned long long a3 = pack2(a.w, a.w);
                fma2(acc[0][0], a0, bv.x); fma2(acc[0][1], a0, bv.y);
                fma2(acc[1][0], a1, bv.x); fma2(acc[1][1], a1, bv.y);
                fma2(acc[2][0], a2, bv.x); fma2(acc[2][1], a2, bv.y);
                fma2(acc[3][0], a3, bv.x); fma2(acc[3][1], a3, bv.y);
            }
        }
        // ---- per-subarray ADC epilogue ----
        #pragma unroll
        for (int mi = 0; mi < 4; mi++) {
            float s0, s1, s2, s3;
            unpack2(acc[mi][0], s0, s1);
            unpack2(acc[mi][1], s2, s3);
            tot[mi][0] += adc_q(s0 * C);
            tot[mi][1] += adc_q(s1 * C);
            tot[mi][2] += adc_q(s2 * C);
            tot[mi][3] += adc_q(s3 * C);
            acc[mi][0] = 0ULL; acc[mi][1] = 0ULL;
        }
    }

    // ---- write out: out[b, o, l] ----
    #pragma unroll
    for (int mi = 0; mi < 4; mi++) {
        int mo = m0 + tm0 + mi;
        int bo = mo >> 10;
        int lo = mo & 1023;
        #pragma unroll
        for (int ni = 0; ni < 4; ni++) {
            int o = n0 + tn0 + ni;
            out[(bo * OC + o) * LSP + lo] = tot[mi][ni];
        }
    }
}

__global__ void tail_zero_kernel(float* __restrict__ out, int start, int total) {
    int i = start + blockIdx.x * blockDim.x + threadIdx.x;
    if (i < total) out[i] = 0.f;
}

// ---------------------------------------------------------------------------
extern "C" void kernel_launch(void* const* d_in, const int* in_sizes, int n_in,
                              void* d_out, int out_size) {
    // Disambiguate input order by element counts.
    const float* x = (const float*)d_in[0];
    const float* w = (const float*)d_in[1];
    if (n_in >= 2 && in_sizes[0] == NW && in_sizes[1] == NX) {
        x = (const float*)d_in[1];
        w = (const float*)d_in[0];
    }
    float* out = (float*)d_out;

    init_kernel<<<1, 1>>>();
    absmax_kernel<<<1024, 256>>>(x, NX, 0);
    absmax_kernel<<<256, 256>>>(w, NW, 1);
    quant_act_kernel<<<(NX + 255) / 256, 256>>>(x);
    quant_w_kernel<<<(NW + 255) / 256, 256>>>(w);

    dim3 grid(32768 / BM, OC / BN);   // 512 x 4
    conv_main_kernel<<<grid, 256>>>(out);

    if (out_size > NOUT) {
        int rem = out_size - NOUT;
        tail_zero_kernel<<<(rem + 255) / 256, 256>>>(out, NOUT, out_size);
    }
}

// round 2
// speedup vs baseline: 1.0003x; 1.0003x over previous
#include <cuda_runtime.h>
#include <cstdint>

// Problem dims
#define NB   32
#define CIN  256
#define HW   32
#define OC   256
#define LSP  1024            // 32*32 spatial
#define KDIM 2304            // 256*9
#define NSUB 9
#define SUBSZ 256
#define NX   (NB*CIN*HW*HW)  // 8388608
#define NW   (OC*KDIM)       // 589824
#define NOUT (NB*OC*LSP)     // 8388608

// Scratch (device globals: allocation-free per harness rules)
__device__ unsigned g_maxbits[2];         // [0]=max|x| bits, [1]=max|w| bits
__device__ float    g_aq[NX];             // quantized activations (integers as f32)
__device__ float    g_wq[KDIM * OC];      // quantized weights, transposed [k][o]

// ---------------------------------------------------------------------------
__global__ void init_kernel() { g_maxbits[0] = 0u; g_maxbits[1] = 0u; }

__global__ void absmax_kernel(const float* __restrict__ p, int n, int slot) {
    float m = 0.f;
    for (int i = blockIdx.x * blockDim.x + threadIdx.x; i < n;
         i += gridDim.x * blockDim.x)
        m = fmaxf(m, fabsf(p[i]));
    #pragma unroll
    for (int o = 16; o; o >>= 1) m = fmaxf(m, __shfl_xor_sync(~0u, m, o));
    __shared__ float sm[32];
    int lane = threadIdx.x & 31, w = threadIdx.x >> 5;
    if (lane == 0) sm[w] = m;
    __syncthreads();
    if (w == 0) {
        m = (lane < (int)(blockDim.x >> 5)) ? sm[lane] : 0.f;
        #pragma unroll
        for (int o = 16; o; o >>= 1) m = fmaxf(m, __shfl_xor_sync(~0u, m, o));
        if (lane == 0) atomicMax(&g_maxbits[slot], __float_as_uint(m));
    }
}

// qa_int = rint(x / s * 255)  (exact integer in [-255,255], stored as f32)
__global__ void quant_act_kernel(const float* __restrict__ x) {
    float s = __uint_as_float(g_maxbits[0]) + 1e-12f;
    int i = blockIdx.x * blockDim.x + threadIdx.x;
    if (i < NX) g_aq[i] = rintf(x[i] / s * 255.f);
}

// qw_int = rint(w / s * 15), transposed to [k][o] for coalesced B-tile loads
__global__ void quant_w_kernel(const float* __restrict__ w) {
    float s = __uint_as_float(g_maxbits[1]) + 1e-12f;
    int i = blockIdx.x * blockDim.x + threadIdx.x;
    if (i < NW) {
        int o = i / KDIM, k = i - o * KDIM;
        g_wq[k * OC + o] = rintf(w[i] / s * 15.f);
    }
}

// ---------------------------------------------------------------------------
// packed 2-wide fp32 FMA (Blackwell f32x2) helpers
__device__ __forceinline__ void fma2(unsigned long long& acc,
                                     unsigned long long a,
                                     unsigned long long b) {
    asm("fma.rn.f32x2 %0, %1, %2, %0;" : "+l"(acc) : "l"(a), "l"(b));
}
__device__ __forceinline__ unsigned long long pack2(float lo, float hi) {
    unsigned long long r;
    asm("mov.b64 %0, {%1, %2};" : "=l"(r) : "f"(lo), "f"(hi));
    return r;
}
__device__ __forceinline__ void unpack2(unsigned long long v, float& lo, float& hi) {
    asm("mov.b64 {%0, %1}, %2;" : "=f"(lo), "=f"(hi) : "l"(v));
}

__device__ __forceinline__ float adc_q(float I) {
    float q = rintf(I / 0.001f);          // matches jnp.round(I / ADC_STEP)
    q = fminf(fmaxf(q, -128.f), 127.f);   // clip to [-2^7, 2^7-1]
    return q * 0.001f;
}

// ---------------------------------------------------------------------------
// Implicit GEMM: out[m, n] = sum_g ADC(C * sum_{i in group g} A[m,i] * W[n,i])
//   m = b*1024 + y*32 + x,  i = c*9 + ky*3 + kx
// BM=64, BN=64, KC=32, 256 threads, each thread -> 4x4 outputs.
#define BM 64
#define BN 64
#define KC 32

__global__ __launch_bounds__(256)
void conv_main_kernel(float* __restrict__ out) {
    __shared__ float As[KC][BM];
    __shared__ float Bs[KC][BN];

    const int m0 = blockIdx.x * BM;     // gridDim.x = 512
    const int n0 = blockIdx.y * BN;     // gridDim.y = 4
    const int t  = threadIdx.x;
    const int tm0 = (t >> 4) << 2;      // 0..60
    const int tn0 = (t & 15) << 2;      // 0..60

    const float sa = __uint_as_float(g_maxbits[0]) + 1e-12f;
    const float sw = __uint_as_float(g_maxbits[1]) + 1e-12f;
    const float C = (float)((double)sa / 255.0 * 0.125 *
                            (double)sw / 15.0 * (0.999 / 15.0));

    // A-load geometry (fixed per thread): column mm, rows (t>>6)+4j
    const int mm = t & 63;
    const int m  = m0 + mm;
    const int b  = m >> 10;
    const int l  = m & 1023;
    const int ycoord = l >> 5;
    const int xcoord = l & 31;
    const int abase  = b * (CIN * LSP);
    const int klbase = t >> 6;          // 0..3
    const int nnB    = t & 63;          // B-load column
    const int klbaseB = t >> 6;

    unsigned long long acc[4][2];
    float tot[4][4];
    #pragma unroll
    for (int i = 0; i < 4; i++) {
        acc[i][0] = 0ULL; acc[i][1] = 0ULL;
        #pragma unroll
        for (int j = 0; j < 4; j++) tot[i][j] = 0.f;
    }

    for (int g = 0; g < NSUB; g++) {
        for (int cc = 0; cc < SUBSZ / KC; cc++) {   // 8 chunks per group
            const int i0 = g * SUBSZ + cc * KC;
            __syncthreads();
            // ---- load A tile (gather with padding) ----
            #pragma unroll
            for (int j = 0; j < 8; j++) {
                int kl = klbase + j * 4;
                int i  = i0 + kl;
                unsigned c  = (unsigned)i / 9u;
                unsigned kk = (unsigned)i - 9u * c;
                int ky = (int)kk / 3;
                int kx = (int)kk - 3 * ky;
                int yy = ycoord + ky - 1;
                int xx = xcoord + kx - 1;
                float v = 0.f;
                if ((unsigned)yy < 32u && (unsigned)xx < 32u)
                    v = g_aq[abase + ((int)c * 32 + yy) * 32 + xx];
                As[kl][mm] = v;
            }
            // ---- load B tile (coalesced) ----
            #pragma unroll
            for (int j = 0; j < 8; j++) {
                int kl = klbaseB + j * 4;
                Bs[kl][nnB] = g_wq[(i0 + kl) * OC + n0 + nnB];
            }
            __syncthreads();
            // ---- compute ----
            #pragma unroll
            for (int kk = 0; kk < KC; kk++) {
                float4 a = *(const float4*)&As[kk][tm0];
                const ulonglong2 bv = *(const ulonglong2*)&Bs[kk][tn0];
                unsigned long long a0 = pack2(a.x, a.x);
                unsigned long long a1 = pack2(a.y, a.y);
                unsigned long long a2 = pack2(a.z, a.z);
                unsigned long long a3 = pack2(a.w, a.w);
                fma2(acc[0][0], a0, bv.x); fma2(acc[0][1], a0, bv.y);
                fma2(acc[1][0], a1, bv.x); fma2(acc[1][1], a1, bv.y);
                fma2(acc[2][0], a2, bv.x); fma2(acc[2][1], a2, bv.y);
                fma2(acc[3][0], a3, bv.x); fma2(acc[3][1], a3, bv.y);
            }
        }
        // ---- per-subarray ADC epilogue ----
        #pragma unroll
        for (int mi = 0; mi < 4; mi++) {
            float s0, s1, s2, s3;
            unpack2(acc[mi][0], s0, s1);
            unpack2(acc[mi][1], s2, s3);
            tot[mi][0] += adc_q(s0 * C);
            tot[mi][1] += adc_q(s1 * C);
            tot[mi][2] += adc_q(s2 * C);
            tot[mi][3] += adc_q(s3 * C);
            acc[mi][0] = 0ULL; acc[mi][1] = 0ULL;
        }
    }

    // ---- write out: out[b, o, l] ----
    #pragma unroll
    for (int mi = 0; mi < 4; mi++) {
        int mo = m0 + tm0 + mi;
        int bo = mo >> 10;
        int lo = mo & 1023;
        #pragma unroll
        for (int ni = 0; ni < 4; ni++) {
            int o = n0 + tn0 + ni;
            out[(bo * OC + o) * LSP + lo] = tot[mi][ni];
        }
    }
}

__global__ void tail_zero_kernel(float* __restrict__ out, int start, int total) {
    int i = start + blockIdx.x * blockDim.x + threadIdx.x;
    if (i < total) out[i] = 0.f;
}

// ---------------------------------------------------------------------------
extern "C" void kernel_launch(void* const* d_in, const int* in_sizes, int n_in,
                              void* d_out, int out_size) {
    // Disambiguate input order by element counts.
    const float* x = (const float*)d_in[0];
    const float* w = (const float*)d_in[1];
    if (n_in >= 2 && in_sizes[0] == NW && in_sizes[1] == NX) {
        x = (const float*)d_in[1];
        w = (const float*)d_in[0];
    }
    float* out = (float*)d_out;

    init_kernel<<<1, 1>>>();
    absmax_kernel<<<1024, 256>>>(x, NX, 0);
    absmax_kernel<<<256, 256>>>(w, NW, 1);
    quant_act_kernel<<<(NX + 255) / 256, 256>>>(x);
    quant_w_kernel<<<(NW + 255) / 256, 256>>>(w);

    dim3 grid(32768 / BM, OC / BN);   // 512 x 4
    conv_main_kernel<<<grid, 256>>>(out);

    if (out_size > NOUT) {
        int rem = out_size - NOUT;
        tail_zero_kernel<<<(rem + 255) / 256, 256>>>(out, NOUT, out_size);
    }
}

// round 4
// speedup vs baseline: 3.4330x; 3.4319x over previous
#include <cuda_runtime.h>
#include <cuda_bf16.h>
#include <cstdint>

// Problem dims
#define NB   32
#define CIN  256
#define OC   256
#define LSP  1024            // 32*32 spatial
#define KDIM 2304            // 256*9
#define MTOT 32768           // NB*LSP
#define NX   (NB*CIN*LSP)    // 8388608
#define NW   (OC*KDIM)       // 589824
#define NOUT (NB*OC*LSP)     // 8388608

// ---------------- device scratch (no allocation allowed) -------------------
__device__ unsigned       g_maxbits[2];                 // [0]=max|x|, [1]=max|w|
__device__ __nv_bfloat16  g_aT[(size_t)KDIM * MTOT];    // 151 MB: A^T [k][m]
__device__ __nv_bfloat16  g_wqT[NW];                    // bf16 weights [o][k]

// ---------------- PTX helpers ----------------------------------------------
__device__ __forceinline__ uint32_t smem_u32(const void* p) {
    uint32_t a;
    asm("{ .reg .u64 t; cvta.to.shared.u64 t, %1; cvt.u32.u64 %0, t; }"
        : "=r"(a) : "l"(p));
    return a;
}
// swizzle for 128B-row tiles (B): XOR bits[6:4] with bits[9:7]
#define SWZ128(o) ((o) ^ (((o) >> 3) & 0x70))
// swizzle for 256B-row tiles (A^T): XOR bits[6:4] with bits[10:8] (row&7)*16
#define SWZB(o)   ((o) ^ (((o) >> 4) & 0x70))

#define CP16(dst, src) asm volatile( \
    "cp.async.cg.shared.global [%0], [%1], 16;" :: "r"(dst), "l"(src) : "memory")
#define CP_COMMIT() asm volatile("cp.async.commit_group;" ::: "memory")
#define CP_WAIT1() asm volatile("cp.async.wait_group 1;" ::: "memory")
#define CP_WAIT0() asm volatile("cp.async.wait_group 0;" ::: "memory")

#define LDSM_X4(r, a) asm volatile( \
    "ldmatrix.sync.aligned.m8n8.x4.shared.b16 {%0,%1,%2,%3}, [%4];" \
    : "=r"((r)[0]), "=r"((r)[1]), "=r"((r)[2]), "=r"((r)[3]) : "r"(a))
#define LDSM_X4T(r, a) asm volatile( \
    "ldmatrix.sync.aligned.m8n8.x4.trans.shared.b16 {%0,%1,%2,%3}, [%4];" \
    : "=r"((r)[0]), "=r"((r)[1]), "=r"((r)[2]), "=r"((r)[3]) : "r"(a))

__device__ __forceinline__ void mma_a(float* d, const uint32_t* a, const uint32_t* b) {
    asm volatile(
        "mma.sync.aligned.m16n8k16.row.col.f32.bf16.bf16.f32 "
        "{%0,%1,%2,%3}, {%4,%5,%6,%7}, {%8,%9}, {%0,%1,%2,%3};"
        : "+f"(d[0]), "+f"(d[1]), "+f"(d[2]), "+f"(d[3])
        : "r"(a[0]), "r"(a[1]), "r"(a[2]), "r"(a[3]), "r"(b[0]), "r"(b[1]));
}
__device__ __forceinline__ void mma_z(float* d, const uint32_t* a, const uint32_t* b) {
    asm volatile(
        "mma.sync.aligned.m16n8k16.row.col.f32.bf16.bf16.f32 "
        "{%0,%1,%2,%3}, {%4,%5,%6,%7}, {%8,%9}, {%10,%10,%10,%10};"
        : "=f"(d[0]), "=f"(d[1]), "=f"(d[2]), "=f"(d[3])
        : "r"(a[0]), "r"(a[1]), "r"(a[2]), "r"(a[3]), "r"(b[0]), "r"(b[1]),
          "f"(0.f));
}

// ---------------- prep kernels ---------------------------------------------
__global__ void init_kernel() { g_maxbits[0] = 0u; g_maxbits[1] = 0u; }

__global__ void absmax_kernel(const float* __restrict__ p, int n, int slot) {
    float m = 0.f;
    for (int i = blockIdx.x * blockDim.x + threadIdx.x; i < n;
         i += gridDim.x * blockDim.x)
        m = fmaxf(m, fabsf(p[i]));
    #pragma unroll
    for (int o = 16; o; o >>= 1) m = fmaxf(m, __shfl_xor_sync(~0u, m, o));
    __shared__ float sm[32];
    int lane = threadIdx.x & 31, w = threadIdx.x >> 5;
    if (lane == 0) sm[w] = m;
    __syncthreads();
    if (w == 0) {
        m = (lane < (int)(blockDim.x >> 5)) ? sm[lane] : 0.f;
        #pragma unroll
        for (int o = 16; o; o >>= 1) m = fmaxf(m, __shfl_xor_sync(~0u, m, o));
        if (lane == 0) atomicMax(&g_maxbits[slot], __float_as_uint(m));
    }
}

__global__ void quant_w_kernel(const float* __restrict__ w) {
    float s = __uint_as_float(g_maxbits[1]) + 1e-12f;
    int i = (blockIdx.x * blockDim.x + threadIdx.x) * 2;
    if (i < NW) {
        float2 v = *(const float2*)(w + i);
        __nv_bfloat162 r;
        r.x = __float2bfloat16(rintf(v.x / s * 15.f));
        r.y = __float2bfloat16(rintf(v.y / s * 15.f));
        *(__nv_bfloat162*)(g_wqT + i) = r;
    }
}

// A^T builder: block.x = k index (2304), block.y = m-slab (16 x 2048 m).
// g_aT[k][m] = quantized x[b, c, y+ky, x+kx] (shifted plane copy, coalesced).
__global__ __launch_bounds__(256) void im2col_t_kernel(const float* __restrict__ x) {
    const float sa = __uint_as_float(g_maxbits[0]) + 1e-12f;
    const int k = blockIdx.x;
    const int c = k / 9, r = k - 9 * c;
    const int ky = r / 3 - 1, kx = (r - (r / 3) * 3) - 1;
    const int mbase = blockIdx.y * 2048;

    #pragma unroll
    for (int j = 0; j < 4; j++) {
        int m = mbase + (threadIdx.x + j * 256) * 2;
        __nv_bfloat162 pv;
        #pragma unroll
        for (int e = 0; e < 2; e++) {
            int mm = m + e;
            int b = mm >> 10, y = (mm >> 5) & 31, xc = mm & 31;
            int ys = y + ky, xs = xc + kx;
            float v = 0.f;
            if ((unsigned)ys < 32u && (unsigned)xs < 32u)
                v = x[((b * 256 + c) << 10) + (ys << 5) + xs];
            __nv_bfloat16 q = __float2bfloat16(rintf(v / sa * 255.f));
            if (e == 0) pv.x = q; else pv.y = q;
        }
        *(__nv_bfloat162*)(g_aT + (size_t)k * MTOT + m) = pv;
    }
}

// ---------------- main HMMA GEMM kernel -------------------------------------
// CTA tile 128(M) x 128(N); 8 warps, warp tile 32x64 (2x8 m16n8k16 tiles).
// K chunks of 64, double-buffered via cp.async. Per-group ADC epilogue.
#define SM_TOTAL 66560

extern __shared__ char gsm[];

__global__ __launch_bounds__(256) void hgemm_kernel(float* __restrict__ out) {
    const uint32_t sb = smem_u32(gsm);
    const int tid = threadIdx.x, lane = tid & 31, wid = tid >> 5;
    const int wm = wid & 3, wn = wid >> 2;
    const int n0 = blockIdx.x * 128;       // gridDim.x = 2
    const int m0 = blockIdx.y * 128;       // gridDim.y = 256

    const uint32_t Aoff[2] = { 0u, 16384u };
    const uint32_t Boff[2] = { 32768u, 49152u };

    const float sa = __uint_as_float(g_maxbits[0]) + 1e-12f;
    const float sw = __uint_as_float(g_maxbits[1]) + 1e-12f;
    const float scaleQ = (float)((double)sa / 255.0 * 0.125 *
                                 (double)sw / 15.0 * (0.999 / 15.0) * 1000.0);

    // per-lane ldmatrix address components
    const int a_kr  = ((lane >> 4) << 3) + (lane & 7);          // k row within 16
    const int a_mc2 = (wm * 32 + ((lane >> 3) & 1) * 8) * 2;    // m byte col
    const int b_nr  = wn * 64 + ((lane >> 4) << 3) + (lane & 7);
    const int b_kc  = ((lane >> 3) & 1) * 16;

    float acc[2][8][4];
    float tot[2][8][4];
    #pragma unroll
    for (int mi = 0; mi < 2; mi++)
        #pragma unroll
        for (int ni = 0; ni < 8; ni++)
            #pragma unroll
            for (int e = 0; e < 4; e++) tot[mi][ni][e] = 0.f;

    auto load_chunk = [&](int n) {
        const int s = n & 1, koff = n * 64;
        const uint32_t abuf = sb + Aoff[s], bbuf = sb + Boff[s];
        #pragma unroll
        for (int j = 0; j < 4; j++) {
            int seg = tid + j * 256;
            int akr = seg >> 4, asm_ = seg & 15;
            const void* asrc = g_aT + (size_t)(koff + akr) * MTOT + m0 + asm_ * 8;
            CP16(abuf + SWZB((uint32_t)(akr * 256 + asm_ * 16)), asrc);
            int br = seg >> 3, bk = seg & 7;
            const void* bsrc = g_wqT + (size_t)(n0 + br) * KDIM + koff + bk * 8;
            CP16(bbuf + SWZ128((uint32_t)(br * 128 + bk * 16)), bsrc);
        }
    };

    load_chunk(0);
    CP_COMMIT();

    for (int n = 0; n < 36; n++) {
        if (n < 35) { load_chunk(n + 1); CP_COMMIT(); CP_WAIT1(); }
        else        { CP_WAIT0(); }
        __syncthreads();

        const int s = n & 1;
        const uint32_t abuf = sb + Aoff[s], bbuf = sb + Boff[s];
        const bool first = ((n & 3) == 0);

        #pragma unroll
        for (int ks = 0; ks < 4; ks++) {
            uint32_t af[2][4];
            #pragma unroll
            for (int mi = 0; mi < 2; mi++) {
                uint32_t off = (uint32_t)((ks * 16 + a_kr) * 256 + a_mc2 + mi * 32);
                LDSM_X4T(af[mi], abuf + SWZB(off));
            }
            uint32_t bf[4][4];
            #pragma unroll
            for (int nb = 0; nb < 4; nb++) {
                uint32_t off = (uint32_t)((b_nr + nb * 16) * 128 + ks * 32 + b_kc);
                LDSM_X4(bf[nb], bbuf + SWZ128(off));
            }
            #pragma unroll
            for (int mi = 0; mi < 2; mi++)
                #pragma unroll
                for (int ni = 0; ni < 8; ni++) {
                    const uint32_t* bp = &bf[ni >> 1][(ni & 1) * 2];
                    if (first && ks == 0) mma_z(acc[mi][ni], af[mi], bp);
                    else                  mma_a(acc[mi][ni], af[mi], bp);
                }
        }
        __syncthreads();

        if ((n & 3) == 3) {   // group boundary: ADC + accumulate
            #pragma unroll
            for (int mi = 0; mi < 2; mi++)
                #pragma unroll
                for (int ni = 0; ni < 8; ni++)
                    #pragma unroll
                    for (int e = 0; e < 4; e++) {
                        float q = rintf(acc[mi][ni][e] * scaleQ);
                        q = fminf(fmaxf(q, -128.f), 127.f);
                        tot[mi][ni][e] += q;
                    }
        }
    }

    // ---- stage warp tile (32m x 64n) in smem, then coalesced global stores --
    float* st = (float*)(gsm + wid * 8320);      // 32 x 65 floats
    #pragma unroll
    for (int mi = 0; mi < 2; mi++)
        #pragma unroll
        for (int ni = 0; ni < 8; ni++)
            #pragma unroll
            for (int e = 0; e < 4; e++) {
                int row = mi * 16 + (lane >> 2) + (e >> 1) * 8;
                int col = ni * 8 + (lane & 3) * 2 + (e & 1);
                st[row * 65 + col] = tot[mi][ni][e] * 0.001f;
            }
    __syncwarp();

    const int mg = m0 + wm * 32;
    const int bb = mg >> 10, l0 = mg & 1023;
    const size_t obase = ((size_t)(bb * 256 + n0 + wn * 64) << 10) + l0 + lane;
    #pragma unroll 8
    for (int o = 0; o < 64; o++)
        out[obase + ((size_t)o << 10)] = st[lane * 65 + o];
}

__global__ void tail_zero_kernel(float* __restrict__ out, int start, int total) {
    int i = start + blockIdx.x * blockDim.x + threadIdx.x;
    if (i < total) out[i] = 0.f;
}

// ---------------------------------------------------------------------------
extern "C" void kernel_launch(void* const* d_in, const int* in_sizes, int n_in,
                              void* d_out, int out_size) {
    const float* x = (const float*)d_in[0];
    const float* w = (const float*)d_in[1];
    if (n_in >= 2 && in_sizes[0] == NW && in_sizes[1] == NX) {
        x = (const float*)d_in[1];
        w = (const float*)d_in[0];
    }
    float* out = (float*)d_out;

    init_kernel<<<1, 1>>>();
    absmax_kernel<<<1024, 256>>>(x, NX, 0);
    absmax_kernel<<<256, 256>>>(w, NW, 1);
    quant_w_kernel<<<(NW / 2 + 255) / 256, 256>>>(w);
    dim3 g_im(KDIM, 16);
    im2col_t_kernel<<<g_im, 256>>>(x);

    cudaFuncSetAttribute(hgemm_kernel,
                         cudaFuncAttributeMaxDynamicSharedMemorySize, SM_TOTAL);
    dim3 grid(OC / 128, MTOT / 128);   // 2 x 256
    hgemm_kernel<<<grid, 256, SM_TOTAL>>>(out);

    if (out_size > NOUT) {
        int rem = out_size - NOUT;
        tail_zero_kernel<<<(rem + 255) / 256, 256>>>(out, NOUT, out_size);
    }
}

// round 5
// speedup vs baseline: 4.5857x; 1.3357x over previous
#include <cuda_runtime.h>
#include <cuda_bf16.h>
#include <cstdint>

// Problem dims
#define NB   32
#define CIN  256
#define OC   256
#define LSP  1024            // 32*32 spatial
#define KDIM 2304            // 256*9
#define MTOT 32768           // NB*LSP
#define NX   (NB*CIN*LSP)    // 8388608
#define NW   (OC*KDIM)       // 589824
#define NOUT (NB*OC*LSP)     // 8388608

// ---------------- device scratch (no allocation allowed) -------------------
__device__ unsigned       g_maxbits[2];                 // [0]=max|x|, [1]=max|w|
__device__ __nv_bfloat16  g_aT[(size_t)KDIM * MTOT];    // 151 MB: A^T [k][m]
__device__ __nv_bfloat16  g_wqT[NW];                    // bf16 weights [o][k]

// ---------------- PTX helpers ----------------------------------------------
__device__ __forceinline__ uint32_t smem_u32(const void* p) {
    uint32_t a;
    asm("{ .reg .u64 t; cvta.to.shared.u64 t, %1; cvt.u32.u64 %0, t; }"
        : "=r"(a) : "l"(p));
    return a;
}
// swizzle for 128B-row tiles (B): XOR bits[6:4] with bits[9:7]
#define SWZ128(o) ((o) ^ (((o) >> 3) & 0x70))
// swizzle for 256B-row tiles (A^T): XOR bits[6:4] with bits[10:8]
#define SWZB(o)   ((o) ^ (((o) >> 4) & 0x70))

#define CP16(dst, src) asm volatile( \
    "cp.async.cg.shared.global [%0], [%1], 16;" :: "r"(dst), "l"(src) : "memory")
#define CP_COMMIT() asm volatile("cp.async.commit_group;" ::: "memory")
#define CP_WAIT1() asm volatile("cp.async.wait_group 1;" ::: "memory")
#define CP_WAIT0() asm volatile("cp.async.wait_group 0;" ::: "memory")

#define LDSM_X4(r, a) asm volatile( \
    "ldmatrix.sync.aligned.m8n8.x4.shared.b16 {%0,%1,%2,%3}, [%4];" \
    : "=r"((r)[0]), "=r"((r)[1]), "=r"((r)[2]), "=r"((r)[3]) : "r"(a))
#define LDSM_X4T(r, a) asm volatile( \
    "ldmatrix.sync.aligned.m8n8.x4.trans.shared.b16 {%0,%1,%2,%3}, [%4];" \
    : "=r"((r)[0]), "=r"((r)[1]), "=r"((r)[2]), "=r"((r)[3]) : "r"(a))

__device__ __forceinline__ void mma_a(float* d, const uint32_t* a, const uint32_t* b) {
    asm volatile(
        "mma.sync.aligned.m16n8k16.row.col.f32.bf16.bf16.f32 "
        "{%0,%1,%2,%3}, {%4,%5,%6,%7}, {%8,%9}, {%0,%1,%2,%3};"
        : "+f"(d[0]), "+f"(d[1]), "+f"(d[2]), "+f"(d[3])
        : "r"(a[0]), "r"(a[1]), "r"(a[2]), "r"(a[3]), "r"(b[0]), "r"(b[1]));
}
__device__ __forceinline__ void mma_z(float* d, const uint32_t* a, const uint32_t* b) {
    asm volatile(
        "mma.sync.aligned.m16n8k16.row.col.f32.bf16.bf16.f32 "
        "{%0,%1,%2,%3}, {%4,%5,%6,%7}, {%8,%9}, {%10,%10,%10,%10};"
        : "=f"(d[0]), "=f"(d[1]), "=f"(d[2]), "=f"(d[3])
        : "r"(a[0]), "r"(a[1]), "r"(a[2]), "r"(a[3]), "r"(b[0]), "r"(b[1]),
          "f"(0.f));
}

// ---------------- kernel 1: init scales + zero output tail -----------------
__global__ void init_tail_kernel(float* __restrict__ out, int start, int total) {
    if (blockIdx.x == 0 && threadIdx.x == 0) { g_maxbits[0] = 0u; g_maxbits[1] = 0u; }
    int i = start + blockIdx.x * blockDim.x + threadIdx.x;
    if (i < total) out[i] = 0.f;
}

// ---------------- kernel 2: fused absmax over x and w ----------------------
__global__ void absmax_fused_kernel(const float* __restrict__ x,
                                    const float* __restrict__ w) {
    const bool isw = (blockIdx.x >= 1024);
    const float* p = isw ? w : x;
    const int n4 = (isw ? NW : NX) >> 2;
    const int b0 = isw ? (blockIdx.x - 1024) : blockIdx.x;
    const int nb = isw ? 256 : 1024;

    float m = 0.f;
    for (int i = b0 * blockDim.x + threadIdx.x; i < n4; i += nb * blockDim.x) {
        float4 v = ((const float4*)p)[i];
        m = fmaxf(m, fmaxf(fmaxf(fabsf(v.x), fabsf(v.y)),
                           fmaxf(fabsf(v.z), fabsf(v.w))));
    }
    #pragma unroll
    for (int o = 16; o; o >>= 1) m = fmaxf(m, __shfl_xor_sync(~0u, m, o));
    __shared__ float sm[32];
    int lane = threadIdx.x & 31, wd = threadIdx.x >> 5;
    if (lane == 0) sm[wd] = m;
    __syncthreads();
    if (wd == 0) {
        m = (lane < (int)(blockDim.x >> 5)) ? sm[lane] : 0.f;
        #pragma unroll
        for (int o = 16; o; o >>= 1) m = fmaxf(m, __shfl_xor_sync(~0u, m, o));
        if (lane == 0) atomicMax(&g_maxbits[isw ? 1 : 0], __float_as_uint(m));
    }
}

// ---------------- kernel 3: fused quant_w + im2col(quant inline) -----------
// blocks [0,1152): quantize w -> g_wqT.  blocks [1152, 1152+2304*16): im2col.
__global__ __launch_bounds__(256) void prep_fused_kernel(const float* __restrict__ x,
                                                         const float* __restrict__ w) {
    if (blockIdx.x < 1152) {
        float s = __uint_as_float(g_maxbits[1]) + 1e-12f;
        int i = (blockIdx.x * blockDim.x + threadIdx.x) * 2;
        if (i < NW) {
            float2 v = *(const float2*)(w + i);
            __nv_bfloat162 r;
            r.x = __float2bfloat16(rintf(v.x / s * 15.f));
            r.y = __float2bfloat16(rintf(v.y / s * 15.f));
            *(__nv_bfloat162*)(g_wqT + i) = r;
        }
        return;
    }
    const float sa = __uint_as_float(g_maxbits[0]) + 1e-12f;
    const float inv = 255.f / sa;
    const int idx = blockIdx.x - 1152;
    const int k = idx >> 4;                 // 0..2303
    const int c = k / 9, r = k - 9 * c;
    const int ky = r / 3 - 1, kx = (r - (r / 3) * 3) - 1;
    const int mbase = (idx & 15) * 2048;
    const float* xp = x + ((size_t)c << 10);

    #pragma unroll
    for (int j = 0; j < 4; j++) {
        int m = mbase + (threadIdx.x + j * 256) * 2;
        int b = m >> 10, y = (m >> 5) & 31, xc = m & 31;
        int ys = y + ky;
        __nv_bfloat162 pv;
        if ((unsigned)ys < 32u) {
            const float* row = xp + (((size_t)b << 18) + (ys << 5));
            int x0 = xc + kx, x1 = x0 + 1;
            float v0 = ((unsigned)x0 < 32u) ? row[x0] : 0.f;
            float v1 = ((unsigned)x1 < 32u) ? row[x1] : 0.f;
            pv.x = __float2bfloat16(rintf(v0 * inv));
            pv.y = __float2bfloat16(rintf(v1 * inv));
        } else {
            pv.x = __float2bfloat16(0.f);
            pv.y = __float2bfloat16(0.f);
        }
        *(__nv_bfloat162*)(g_aT + (size_t)k * MTOT + m) = pv;
    }
}

// ---------------- kernel 4: main HMMA GEMM ----------------------------------
// CTA tile 128(M) x 128(N); 8 warps, warp tile 32x64 (2x8 m16n8k16 tiles).
// K chunks of 64, 3-stage cp.async ring, ONE __syncthreads per chunk.
// Per-group (every 4 chunks) ADC epilogue in registers.
#define SM_TOTAL 98304

extern __shared__ char gsm[];

__global__ __launch_bounds__(256) void hgemm_kernel(float* __restrict__ out) {
    const uint32_t sb = smem_u32(gsm);
    const int tid = threadIdx.x, lane = tid & 31, wid = tid >> 5;
    const int wm = wid & 3, wn = wid >> 2;
    const int n0 = blockIdx.x * 128;       // gridDim.x = 2
    const int m0 = blockIdx.y * 128;       // gridDim.y = 256

    // stage s at s*32768: A [0,16K), B [16K,32K)
    const float sa = __uint_as_float(g_maxbits[0]) + 1e-12f;
    const float sw = __uint_as_float(g_maxbits[1]) + 1e-12f;
    const float scaleQ = (float)((double)sa / 255.0 * 0.125 *
                                 (double)sw / 15.0 * (0.999 / 15.0) * 1000.0);

    // per-lane ldmatrix address components
    const int a_kr  = ((lane >> 4) << 3) + (lane & 7);
    const int a_mc2 = (wm * 32 + ((lane >> 3) & 1) * 8) * 2;
    const int b_nr  = wn * 64 + ((lane >> 4) << 3) + (lane & 7);
    const int b_kc  = ((lane >> 3) & 1) * 16;

    float acc[2][8][4];
    float tot[2][8][4];
    #pragma unroll
    for (int mi = 0; mi < 2; mi++)
        #pragma unroll
        for (int ni = 0; ni < 8; ni++)
            #pragma unroll
            for (int e = 0; e < 4; e++) tot[mi][ni][e] = 0.f;

    // per-thread load geometry (hoisted)
    const int l_akr = tid >> 4, l_asm = tid & 15;
    const int l_br  = tid >> 3, l_bk  = tid & 7;
    const __nv_bfloat16* aP = g_aT + (size_t)l_akr * MTOT + m0 + l_asm * 8;
    const __nv_bfloat16* bP = g_wqT + (size_t)(n0 + l_br) * KDIM + l_bk * 8;

    auto load_chunk = [&](int n) {
        const uint32_t st = sb + (uint32_t)(n % 3) * 32768u;
        const int koff = n * 64;
        #pragma unroll
        for (int j = 0; j < 4; j++) {
            CP16(st + SWZB((uint32_t)((l_akr + j * 16) * 256 + l_asm * 16)),
                 aP + (size_t)(koff + j * 16) * MTOT);
            CP16(st + 16384u + SWZ128((uint32_t)((l_br + j * 32) * 128 + l_bk * 16)),
                 bP + (size_t)(j * 32) * KDIM + koff);
        }
    };

    load_chunk(0); CP_COMMIT();
    load_chunk(1); CP_COMMIT();

    for (int n = 0; n < 36; n++) {
        if (n < 35) CP_WAIT1(); else CP_WAIT0();
        __syncthreads();

        const uint32_t st = sb + (uint32_t)(n % 3) * 32768u;
        const uint32_t abuf = st, bbuf = st + 16384u;
        const bool first = ((n & 3) == 0);

        #pragma unroll
        for (int ks = 0; ks < 4; ks++) {
            uint32_t af[2][4];
            #pragma unroll
            for (int mi = 0; mi < 2; mi++) {
                uint32_t off = (uint32_t)((ks * 16 + a_kr) * 256 + a_mc2 + mi * 32);
                LDSM_X4T(af[mi], abuf + SWZB(off));
            }
            uint32_t bf[4][4];
            #pragma unroll
            for (int nb = 0; nb < 4; nb++) {
                uint32_t off = (uint32_t)((b_nr + nb * 16) * 128 + ks * 32 + b_kc);
                LDSM_X4(bf[nb], bbuf + SWZ128(off));
            }
            #pragma unroll
            for (int mi = 0; mi < 2; mi++)
                #pragma unroll
                for (int ni = 0; ni < 8; ni++) {
                    const uint32_t* bp = &bf[ni >> 1][(ni & 1) * 2];
                    if (first && ks == 0) mma_z(acc[mi][ni], af[mi], bp);
                    else                  mma_a(acc[mi][ni], af[mi], bp);
                }
        }

        if (n + 2 < 36) { load_chunk(n + 2); CP_COMMIT(); }

        if ((n & 3) == 3) {   // group boundary: ADC + accumulate
            #pragma unroll
            for (int mi = 0; mi < 2; mi++)
                #pragma unroll
                for (int ni = 0; ni < 8; ni++)
                    #pragma unroll
                    for (int e = 0; e < 4; e++) {
                        float q = rintf(acc[mi][ni][e] * scaleQ);
                        q = fminf(fmaxf(q, -128.f), 127.f);
                        tot[mi][ni][e] += q;
                    }
        }
    }

    // ---- stage warp tile (32m x 64n) in smem, then coalesced global stores --
    __syncthreads();
    float* st = (float*)(gsm + wid * 8320);      // 32 x 65 floats
    #pragma unroll
    for (int mi = 0; mi < 2; mi++)
        #pragma unroll
        for (int ni = 0; ni < 8; ni++)
            #pragma unroll
            for (int e = 0; e < 4; e++) {
                int row = mi * 16 + (lane >> 2) + (e >> 1) * 8;
                int col = ni * 8 + (lane & 3) * 2 + (e & 1);
                st[row * 65 + col] = tot[mi][ni][e] * 0.001f;
            }
    __syncwarp();

    const int mg = m0 + wm * 32;
    const int bb = mg >> 10, l0 = mg & 1023;
    const size_t obase = ((size_t)(bb * 256 + n0 + wn * 64) << 10) + l0 + lane;
    #pragma unroll 8
    for (int o = 0; o < 64; o++)
        out[obase + ((size_t)o << 10)] = st[lane * 65 + o];
}

// ---------------------------------------------------------------------------
extern "C" void kernel_launch(void* const* d_in, const int* in_sizes, int n_in,
                              void* d_out, int out_size) {
    const float* x = (const float*)d_in[0];
    const float* w = (const float*)d_in[1];
    if (n_in >= 2 && in_sizes[0] == NW && in_sizes[1] == NX) {
        x = (const float*)d_in[1];
        w = (const float*)d_in[0];
    }
    float* out = (float*)d_out;

    // launch 1: init scale slots + zero output tail
    int rem = (out_size > NOUT) ? (out_size - NOUT) : 0;
    int tb = (rem > 0) ? (rem + 255) / 256 : 1;
    init_tail_kernel<<<tb, 256>>>(out, NOUT, out_size);

    // launch 2: fused absmax (x: blocks 0-1023, w: blocks 1024-1279)
    absmax_fused_kernel<<<1280, 256>>>(x, w);

    // launch 3: fused quant_w + im2col(quant inline)
    prep_fused_kernel<<<1152 + KDIM * 16, 256>>>(x, w);

    // launch 4: GEMM (this should be the ncu-captured launch)
    cudaFuncSetAttribute(hgemm_kernel,
                         cudaFuncAttributeMaxDynamicSharedMemorySize, SM_TOTAL);
    dim3 grid(OC / 128, MTOT / 128);   // 2 x 256
    hgemm_kernel<<<grid, 256, SM_TOTAL>>>(out);
}

// round 6
// speedup vs baseline: 5.0365x; 1.0983x over previous
#include <cuda_runtime.h>
#include <cuda_bf16.h>
#include <cstdint>

// Problem dims
#define NB   32
#define CIN  256
#define OC   256
#define LSP  1024            // 32*32 spatial
#define KDIM 2304            // 256*9
#define MTOT 32768           // NB*LSP
#define NX   (NB*CIN*LSP)    // 8388608
#define NW   (OC*KDIM)       // 589824
#define NOUT (NB*OC*LSP)     // 8388608

// ---------------- device scratch (no allocation allowed) -------------------
__device__ unsigned       g_maxbits[2];                 // [0]=max|x|, [1]=max|w|
__device__ __nv_bfloat16  g_aT[(size_t)KDIM * MTOT];    // 151 MB: A^T [k][m]
__device__ __nv_bfloat16  g_wqT[NW];                    // bf16 weights [o][k]

// ---------------- PTX helpers ----------------------------------------------
__device__ __forceinline__ uint32_t smem_u32(const void* p) {
    uint32_t a;
    asm("{ .reg .u64 t; cvta.to.shared.u64 t, %1; cvt.u32.u64 %0, t; }"
        : "=r"(a) : "l"(p));
    return a;
}
// swizzle for 256B-row tiles: XOR bits[6:4] with (row&7) = bits[10:8]
#define SWZB(o)   ((o) ^ (((o) >> 4) & 0x70))

#define CP16(dst, src) asm volatile( \
    "cp.async.cg.shared.global [%0], [%1], 16;" :: "r"(dst), "l"(src) : "memory")
#define CP_COMMIT() asm volatile("cp.async.commit_group;" ::: "memory")
#define CP_WAIT1() asm volatile("cp.async.wait_group 1;" ::: "memory")
#define CP_WAIT0() asm volatile("cp.async.wait_group 0;" ::: "memory")

#define LDSM_X4(r, a) asm volatile( \
    "ldmatrix.sync.aligned.m8n8.x4.shared.b16 {%0,%1,%2,%3}, [%4];" \
    : "=r"((r)[0]), "=r"((r)[1]), "=r"((r)[2]), "=r"((r)[3]) : "r"(a))
#define LDSM_X4T(r, a) asm volatile( \
    "ldmatrix.sync.aligned.m8n8.x4.trans.shared.b16 {%0,%1,%2,%3}, [%4];" \
    : "=r"((r)[0]), "=r"((r)[1]), "=r"((r)[2]), "=r"((r)[3]) : "r"(a))

__device__ __forceinline__ void mma_a(float* d, const uint32_t* a, const uint32_t* b) {
    asm volatile(
        "mma.sync.aligned.m16n8k16.row.col.f32.bf16.bf16.f32 "
        "{%0,%1,%2,%3}, {%4,%5,%6,%7}, {%8,%9}, {%0,%1,%2,%3};"
        : "+f"(d[0]), "+f"(d[1]), "+f"(d[2]), "+f"(d[3])
        : "r"(a[0]), "r"(a[1]), "r"(a[2]), "r"(a[3]), "r"(b[0]), "r"(b[1]));
}
__device__ __forceinline__ void mma_z(float* d, const uint32_t* a, const uint32_t* b) {
    asm volatile(
        "mma.sync.aligned.m16n8k16.row.col.f32.bf16.bf16.f32 "
        "{%0,%1,%2,%3}, {%4,%5,%6,%7}, {%8,%9}, {%10,%10,%10,%10};"
        : "=f"(d[0]), "=f"(d[1]), "=f"(d[2]), "=f"(d[3])
        : "r"(a[0]), "r"(a[1]), "r"(a[2]), "r"(a[3]), "r"(b[0]), "r"(b[1]),
          "f"(0.f));
}

// ---------------- kernel 1: init scales + zero output tail -----------------
__global__ void init_tail_kernel(float* __restrict__ out, int start, int total) {
    if (blockIdx.x == 0 && threadIdx.x == 0) { g_maxbits[0] = 0u; g_maxbits[1] = 0u; }
    int i = start + blockIdx.x * blockDim.x + threadIdx.x;
    if (i < total) out[i] = 0.f;
}

// ---------------- kernel 2: fused absmax over x and w ----------------------
__global__ void absmax_fused_kernel(const float* __restrict__ x,
                                    const float* __restrict__ w) {
    const bool isw = (blockIdx.x >= 1024);
    const float* p = isw ? w : x;
    const int n4 = (isw ? NW : NX) >> 2;
    const int b0 = isw ? (blockIdx.x - 1024) : blockIdx.x;
    const int nb = isw ? 256 : 1024;

    float m = 0.f;
    for (int i = b0 * blockDim.x + threadIdx.x; i < n4; i += nb * blockDim.x) {
        float4 v = ((const float4*)p)[i];
        m = fmaxf(m, fmaxf(fmaxf(fabsf(v.x), fabsf(v.y)),
                           fmaxf(fabsf(v.z), fabsf(v.w))));
    }
    #pragma unroll
    for (int o = 16; o; o >>= 1) m = fmaxf(m, __shfl_xor_sync(~0u, m, o));
    __shared__ float sm[32];
    int lane = threadIdx.x & 31, wd = threadIdx.x >> 5;
    if (lane == 0) sm[wd] = m;
    __syncthreads();
    if (wd == 0) {
        m = (lane < (int)(blockDim.x >> 5)) ? sm[lane] : 0.f;
        #pragma unroll
        for (int o = 16; o; o >>= 1) m = fmaxf(m, __shfl_xor_sync(~0u, m, o));
        if (lane == 0) atomicMax(&g_maxbits[isw ? 1 : 0], __float_as_uint(m));
    }
}

// ---------------- kernel 3: fused quant_w + im2col(quant inline) -----------
// blocks [0,1152): quantize w -> g_wqT.  blocks [1152, 1152+2304*16): im2col.
__global__ __launch_bounds__(256) void prep_fused_kernel(const float* __restrict__ x,
                                                         const float* __restrict__ w) {
    if (blockIdx.x < 1152) {
        float s = __uint_as_float(g_maxbits[1]) + 1e-12f;
        int i = (blockIdx.x * blockDim.x + threadIdx.x) * 2;
        if (i < NW) {
            float2 v = *(const float2*)(w + i);
            __nv_bfloat162 r;
            r.x = __float2bfloat16(rintf(v.x / s * 15.f));
            r.y = __float2bfloat16(rintf(v.y / s * 15.f));
            *(__nv_bfloat162*)(g_wqT + i) = r;
        }
        return;
    }
    const float sa = __uint_as_float(g_maxbits[0]) + 1e-12f;
    const float inv = 255.f / sa;
    const int idx = blockIdx.x - 1152;
    const int k = idx >> 4;                 // 0..2303
    const int c = k / 9, r = k - 9 * c;
    const int ky = r / 3 - 1, kx = (r - (r / 3) * 3) - 1;
    // one thread -> 8 consecutive m (same image row), one 16B store
    const int m = (idx & 15) * 2048 + threadIdx.x * 8;
    const int b = m >> 10, y = (m >> 5) & 31, xc = m & 31;
    const int ys = y + ky;

    __nv_bfloat162 q[4];
    if ((unsigned)ys < 32u) {
        const float* row = x + (((size_t)(b * 256 + c) << 10) + (ys << 5));
        #pragma unroll
        for (int e = 0; e < 4; e++) {
            int x0 = xc + kx + 2 * e, x1 = x0 + 1;
            float v0 = ((unsigned)x0 < 32u) ? row[x0] : 0.f;
            float v1 = ((unsigned)x1 < 32u) ? row[x1] : 0.f;
            q[e].x = __float2bfloat16(rintf(v0 * inv));
            q[e].y = __float2bfloat16(rintf(v1 * inv));
        }
    } else {
        #pragma unroll
        for (int e = 0; e < 4; e++)
            q[e].x = q[e].y = __float2bfloat16(0.f);
    }
    *(uint4*)(g_aT + (size_t)k * MTOT + m) = *(const uint4*)q;
}

// ---------------- kernel 4: main HMMA GEMM ----------------------------------
// CTA tile 128(M) x 128(N); 8 warps, warp tile 32x64 (2x8 m16n8k16 tiles).
// K chunks of 128, 3-stage cp.async ring (192 KB smem), ONE sync per chunk,
// double-buffered ldmatrix fragments, per-group (2 chunks) ADC epilogue.
#define SM_TOTAL 196608
#define STAGE    65536

extern __shared__ char gsm[];

__global__ __launch_bounds__(256, 1) void hgemm_kernel(float* __restrict__ out) {
    const uint32_t sb = smem_u32(gsm);
    const int tid = threadIdx.x, lane = tid & 31, wid = tid >> 5;
    const int wm = wid & 3, wn = wid >> 2;
    const int n0 = blockIdx.x * 128;       // gridDim.x = 2
    const int m0 = blockIdx.y * 128;       // gridDim.y = 256

    const float sa = __uint_as_float(g_maxbits[0]) + 1e-12f;
    const float sw = __uint_as_float(g_maxbits[1]) + 1e-12f;
    const float scaleQ = (float)((double)sa / 255.0 * 0.125 *
                                 (double)sw / 15.0 * (0.999 / 15.0) * 1000.0);

    // per-lane ldmatrix address components (256B rows for both tiles)
    const int a_kr  = ((lane >> 4) << 3) + (lane & 7);
    const int a_mc2 = (wm * 32 + ((lane >> 3) & 1) * 8) * 2;
    const int b_nr  = wn * 64 + ((lane >> 4) << 3) + (lane & 7);
    const int b_kc  = ((lane >> 3) & 1) * 16;

    float acc[2][8][4];
    float tot[2][8][4];
    #pragma unroll
    for (int mi = 0; mi < 2; mi++)
        #pragma unroll
        for (int ni = 0; ni < 8; ni++)
            #pragma unroll
            for (int e = 0; e < 4; e++) tot[mi][ni][e] = 0.f;

    // per-thread cp.async geometry: 16 x 16B per tile per chunk
    const int l_r = tid >> 4, l_s = tid & 15;    // row 0..15 (+16*j), seg 0..15
    const __nv_bfloat16* aP = g_aT + (size_t)l_r * MTOT + m0 + l_s * 8;
    const __nv_bfloat16* bP = g_wqT + (size_t)(n0 + l_r) * KDIM + l_s * 8;

    auto load_chunk = [&](int n) {
        const uint32_t st = sb + (uint32_t)(n % 3) * STAGE;
        const int koff = n * 128;
        #pragma unroll
        for (int j = 0; j < 8; j++) {
            CP16(st + SWZB((uint32_t)((l_r + j * 16) * 256 + l_s * 16)),
                 aP + (size_t)(koff + j * 16) * MTOT);
            CP16(st + 32768u + SWZB((uint32_t)((l_r + j * 16) * 256 + l_s * 16)),
                 bP + (size_t)(j * 16) * KDIM + koff);
        }
    };

    load_chunk(0); CP_COMMIT();
    load_chunk(1); CP_COMMIT();

    uint32_t af[2][2][4], bf[2][4][4];

    for (int n = 0; n < 18; n++) {
        if (n < 17) CP_WAIT1(); else CP_WAIT0();
        __syncthreads();

        const uint32_t st = sb + (uint32_t)(n % 3) * STAGE;
        const uint32_t abuf = st, bbuf = st + 32768u;
        const bool first = ((n & 1) == 0);

        // prime ks=0 fragments
        #pragma unroll
        for (int mi = 0; mi < 2; mi++)
            LDSM_X4T(af[0][mi], abuf + SWZB((uint32_t)(a_kr * 256 + a_mc2 + mi * 32)));
        #pragma unroll
        for (int nb = 0; nb < 4; nb++)
            LDSM_X4(bf[0][nb], bbuf + SWZB((uint32_t)((b_nr + nb * 16) * 256 + b_kc)));

        #pragma unroll
        for (int ks = 0; ks < 8; ks++) {
            const int p = ks & 1, q = p ^ 1;
            if (ks < 7) {
                #pragma unroll
                for (int mi = 0; mi < 2; mi++)
                    LDSM_X4T(af[q][mi], abuf + SWZB((uint32_t)(
                        ((ks + 1) * 16 + a_kr) * 256 + a_mc2 + mi * 32)));
                #pragma unroll
                for (int nb = 0; nb < 4; nb++)
                    LDSM_X4(bf[q][nb], bbuf + SWZB((uint32_t)(
                        (b_nr + nb * 16) * 256 + (ks + 1) * 32 + b_kc)));
            }
            #pragma unroll
            for (int mi = 0; mi < 2; mi++)
                #pragma unroll
                for (int ni = 0; ni < 8; ni++) {
                    const uint32_t* bp = &bf[p][ni >> 1][(ni & 1) * 2];
                    if (first && ks == 0) mma_z(acc[mi][ni], af[p][mi], bp);
                    else                  mma_a(acc[mi][ni], af[p][mi], bp);
                }
        }

        if (n + 2 < 18) { load_chunk(n + 2); CP_COMMIT(); }

        if ((n & 1) == 1) {   // group boundary (256 k): ADC + accumulate
            #pragma unroll
            for (int mi = 0; mi < 2; mi++)
                #pragma unroll
                for (int ni = 0; ni < 8; ni++)
                    #pragma unroll
                    for (int e = 0; e < 4; e++) {
                        float q2 = rintf(acc[mi][ni][e] * scaleQ);
                        q2 = fminf(fmaxf(q2, -128.f), 127.f);
                        tot[mi][ni][e] += q2;
                    }
        }
    }

    // ---- stage warp tile (32m x 64n) in smem, then coalesced global stores --
    __syncthreads();
    float* st = (float*)(gsm + wid * 8320);      // 32 x 65 floats
    #pragma unroll
    for (int mi = 0; mi < 2; mi++)
        #pragma unroll
        for (int ni = 0; ni < 8; ni++)
            #pragma unroll
            for (int e = 0; e < 4; e++) {
                int row = mi * 16 + (lane >> 2) + (e >> 1) * 8;
                int col = ni * 8 + (lane & 3) * 2 + (e & 1);
                st[row * 65 + col] = tot[mi][ni][e] * 0.001f;
            }
    __syncwarp();

    const int mg = m0 + wm * 32;
    const int bb = mg >> 10, l0 = mg & 1023;
    const size_t obase = ((size_t)(bb * 256 + n0 + wn * 64) << 10) + l0 + lane;
    #pragma unroll 8
    for (int o = 0; o < 64; o++)
        out[obase + ((size_t)o << 10)] = st[lane * 65 + o];
}

// ---------------------------------------------------------------------------
extern "C" void kernel_launch(void* const* d_in, const int* in_sizes, int n_in,
                              void* d_out, int out_size) {
    const float* x = (const float*)d_in[0];
    const float* w = (const float*)d_in[1];
    if (n_in >= 2 && in_sizes[0] == NW && in_sizes[1] == NX) {
        x = (const float*)d_in[1];
        w = (const float*)d_in[0];
    }
    float* out = (float*)d_out;

    int rem = (out_size > NOUT) ? (out_size - NOUT) : 0;
    int tb = (rem > 0) ? (rem + 255) / 256 : 1;
    init_tail_kernel<<<tb, 256>>>(out, NOUT, out_size);

    absmax_fused_kernel<<<1280, 256>>>(x, w);

    prep_fused_kernel<<<1152 + KDIM * 16, 256>>>(x, w);

    cudaFuncSetAttribute(hgemm_kernel,
                         cudaFuncAttributeMaxDynamicSharedMemorySize, SM_TOTAL);
    dim3 grid(OC / 128, MTOT / 128);   // 2 x 256
    hgemm_kernel<<<grid, 256, SM_TOTAL>>>(out);
}

// round 7
// speedup vs baseline: 5.3931x; 1.0708x over previous
#include <cuda_runtime.h>
#include <cuda_bf16.h>
#include <cstdint>

// Problem dims
#define NB   32
#define CIN  256
#define OC   256
#define LSP  1024            // 32*32 spatial
#define KDIM 2304            // 256*9
#define MTOT 32768           // NB*LSP
#define NX   (NB*CIN*LSP)    // 8388608
#define NW   (OC*KDIM)       // 589824
#define NOUT (NB*OC*LSP)     // 8388608

// ---------------- device scratch (no allocation allowed) -------------------
__device__ unsigned       g_maxbits[2];                 // [0]=max|x|, [1]=max|w|
__device__ __nv_bfloat16  g_aT[(size_t)KDIM * MTOT];    // 151 MB: A^T [k][m]
__device__ __nv_bfloat16  g_wqT[NW];                    // bf16 weights [o][k]

// ---------------- PTX helpers ----------------------------------------------
__device__ __forceinline__ uint32_t smem_u32(const void* p) {
    uint32_t a;
    asm("{ .reg .u64 t; cvta.to.shared.u64 t, %1; cvt.u32.u64 %0, t; }"
        : "=r"(a) : "l"(p));
    return a;
}
// swizzle for 256B-row tiles (A): XOR bits[6:4] with bits[10:8]
#define SWZB(o)   ((o) ^ (((o) >> 4) & 0x70))
// swizzle for 128B-row tiles (B): XOR bits[6:4] with bits[9:7]
#define SWZ128(o) ((o) ^ (((o) >> 3) & 0x70))

#define CP16(dst, src) asm volatile( \
    "cp.async.cg.shared.global [%0], [%1], 16;" :: "r"(dst), "l"(src) : "memory")
#define CP_COMMIT() asm volatile("cp.async.commit_group;" ::: "memory")
#define CP_WAIT1() asm volatile("cp.async.wait_group 1;" ::: "memory")
#define CP_WAIT0() asm volatile("cp.async.wait_group 0;" ::: "memory")

#define LDSM_X4(r, a) asm volatile( \
    "ldmatrix.sync.aligned.m8n8.x4.shared.b16 {%0,%1,%2,%3}, [%4];" \
    : "=r"((r)[0]), "=r"((r)[1]), "=r"((r)[2]), "=r"((r)[3]) : "r"(a))
#define LDSM_X4T(r, a) asm volatile( \
    "ldmatrix.sync.aligned.m8n8.x4.trans.shared.b16 {%0,%1,%2,%3}, [%4];" \
    : "=r"((r)[0]), "=r"((r)[1]), "=r"((r)[2]), "=r"((r)[3]) : "r"(a))

__device__ __forceinline__ void mma_a(float* d, const uint32_t* a, const uint32_t* b) {
    asm volatile(
        "mma.sync.aligned.m16n8k16.row.col.f32.bf16.bf16.f32 "
        "{%0,%1,%2,%3}, {%4,%5,%6,%7}, {%8,%9}, {%0,%1,%2,%3};"
        : "+f"(d[0]), "+f"(d[1]), "+f"(d[2]), "+f"(d[3])
        : "r"(a[0]), "r"(a[1]), "r"(a[2]), "r"(a[3]), "r"(b[0]), "r"(b[1]));
}
__device__ __forceinline__ void mma_z(float* d, const uint32_t* a, const uint32_t* b) {
    asm volatile(
        "mma.sync.aligned.m16n8k16.row.col.f32.bf16.bf16.f32 "
        "{%0,%1,%2,%3}, {%4,%5,%6,%7}, {%8,%9}, {%10,%10,%10,%10};"
        : "=f"(d[0]), "=f"(d[1]), "=f"(d[2]), "=f"(d[3])
        : "r"(a[0]), "r"(a[1]), "r"(a[2]), "r"(a[3]), "r"(b[0]), "r"(b[1]),
          "f"(0.f));
}

// ---------------- kernel 1: init scales + zero output tail -----------------
__global__ void init_tail_kernel(float* __restrict__ out, int start, int total) {
    if (blockIdx.x == 0 && threadIdx.x == 0) { g_maxbits[0] = 0u; g_maxbits[1] = 0u; }
    int i = start + blockIdx.x * blockDim.x + threadIdx.x;
    if (i < total) out[i] = 0.f;
}

// ---------------- kernel 2: fused absmax over x and w ----------------------
__global__ void absmax_fused_kernel(const float* __restrict__ x,
                                    const float* __restrict__ w) {
    const bool isw = (blockIdx.x >= 1024);
    const float* p = isw ? w : x;
    const int n4 = (isw ? NW : NX) >> 2;
    const int b0 = isw ? (blockIdx.x - 1024) : blockIdx.x;
    const int nb = isw ? 256 : 1024;

    float m = 0.f;
    for (int i = b0 * blockDim.x + threadIdx.x; i < n4; i += nb * blockDim.x) {
        float4 v = ((const float4*)p)[i];
        m = fmaxf(m, fmaxf(fmaxf(fabsf(v.x), fabsf(v.y)),
                           fmaxf(fabsf(v.z), fabsf(v.w))));
    }
    #pragma unroll
    for (int o = 16; o; o >>= 1) m = fmaxf(m, __shfl_xor_sync(~0u, m, o));
    __shared__ float sm[32];
    int lane = threadIdx.x & 31, wd = threadIdx.x >> 5;
    if (lane == 0) sm[wd] = m;
    __syncthreads();
    if (wd == 0) {
        m = (lane < (int)(blockDim.x >> 5)) ? sm[lane] : 0.f;
        #pragma unroll
        for (int o = 16; o; o >>= 1) m = fmaxf(m, __shfl_xor_sync(~0u, m, o));
        if (lane == 0) atomicMax(&g_maxbits[isw ? 1 : 0], __float_as_uint(m));
    }
}

// ---------------- kernel 3: fused quant_w + im2col(quant inline) -----------
__global__ __launch_bounds__(256) void prep_fused_kernel(const float* __restrict__ x,
                                                         const float* __restrict__ w) {
    if (blockIdx.x < 1152) {
        float s = __uint_as_float(g_maxbits[1]) + 1e-12f;
        int i = (blockIdx.x * blockDim.x + threadIdx.x) * 2;
        if (i < NW) {
            float2 v = *(const float2*)(w + i);
            __nv_bfloat162 r;
            r.x = __float2bfloat16(rintf(v.x / s * 15.f));
            r.y = __float2bfloat16(rintf(v.y / s * 15.f));
            *(__nv_bfloat162*)(g_wqT + i) = r;
        }
        return;
    }
    const float sa = __uint_as_float(g_maxbits[0]) + 1e-12f;
    const float inv = 255.f / sa;
    const int idx = blockIdx.x - 1152;
    const int k = idx >> 4;                 // 0..2303
    const int c = k / 9, r = k - 9 * c;
    const int ky = r / 3 - 1, kx = (r - (r / 3) * 3) - 1;
    // one thread -> 8 consecutive m (same image row), one 16B store
    const int m = (idx & 15) * 2048 + threadIdx.x * 8;
    const int b = m >> 10, y = (m >> 5) & 31, xc = m & 31;
    const int ys = y + ky;

    __nv_bfloat162 q[4];
    if ((unsigned)ys < 32u) {
        const float* row = x + (((size_t)(b * 256 + c) << 10) + (ys << 5));
        #pragma unroll
        for (int e = 0; e < 4; e++) {
            int x0 = xc + kx + 2 * e, x1 = x0 + 1;
            float v0 = ((unsigned)x0 < 32u) ? row[x0] : 0.f;
            float v1 = ((unsigned)x1 < 32u) ? row[x1] : 0.f;
            q[e].x = __float2bfloat16(rintf(v0 * inv));
            q[e].y = __float2bfloat16(rintf(v1 * inv));
        }
    } else {
        #pragma unroll
        for (int e = 0; e < 4; e++)
            q[e].x = q[e].y = __float2bfloat16(0.f);
    }
    *(uint4*)(g_aT + (size_t)k * MTOT + m) = *(const uint4*)q;
}

// ---------------- kernel 4: main HMMA GEMM ----------------------------------
// CTA tile 128(M) x 64(N); 8 warps (4m x 2n), warp tile 32x32.
// K chunks of 64, 3-stage cp.async ring (72 KB smem), 2 CTAs/SM.
// Per-group (4 chunks = 256 k) ADC epilogue in registers.
#define STAGE    24576                     // A 16 KB + B 8 KB
#define BOFF     16384
#define SM_TOTAL (3 * STAGE)               // 73728

extern __shared__ char gsm[];

__global__ __launch_bounds__(256, 2) void hgemm_kernel(float* __restrict__ out) {
    const uint32_t sb = smem_u32(gsm);
    const int tid = threadIdx.x, lane = tid & 31, wid = tid >> 5;
    const int wm = wid & 3, wn = wid >> 2;
    const int n0 = blockIdx.x * 64;        // gridDim.x = 4
    const int m0 = blockIdx.y * 128;       // gridDim.y = 256

    const float sa = __uint_as_float(g_maxbits[0]) + 1e-12f;
    const float sw = __uint_as_float(g_maxbits[1]) + 1e-12f;
    const float scaleQ = (float)((double)sa / 255.0 * 0.125 *
                                 (double)sw / 15.0 * (0.999 / 15.0) * 1000.0);

    // per-lane ldmatrix address components
    const int a_kr  = ((lane >> 4) << 3) + (lane & 7);
    const int a_mc2 = (wm * 32 + ((lane >> 3) & 1) * 8) * 2;
    const int b_nr  = wn * 32 + ((lane >> 4) << 3) + (lane & 7);
    const int b_kc  = ((lane >> 3) & 1) * 16;

    float acc[2][4][4];
    float tot[2][4][4];
    #pragma unroll
    for (int mi = 0; mi < 2; mi++)
        #pragma unroll
        for (int ni = 0; ni < 4; ni++)
            #pragma unroll
            for (int e = 0; e < 4; e++) tot[mi][ni][e] = 0.f;

    // per-thread cp.async geometry
    const int l_r = tid >> 4, l_s = tid & 15;     // A: 16 rows x 16 segs
    const int l_br = tid >> 3, l_bs = tid & 7;    // B: 32 rows x 8 segs
    const __nv_bfloat16* aP = g_aT + (size_t)l_r * MTOT + m0 + l_s * 8;
    const __nv_bfloat16* bP = g_wqT + (size_t)(n0 + l_br) * KDIM + l_bs * 8;

    auto load_chunk = [&](int n) {
        const uint32_t st = sb + (uint32_t)(n % 3) * STAGE;
        const int koff = n * 64;
        #pragma unroll
        for (int j = 0; j < 4; j++)
            CP16(st + SWZB((uint32_t)((l_r + j * 16) * 256 + l_s * 16)),
                 aP + (size_t)(koff + j * 16) * MTOT);
        #pragma unroll
        for (int j = 0; j < 2; j++)
            CP16(st + BOFF + SWZ128((uint32_t)((l_br + j * 32) * 128 + l_bs * 16)),
                 bP + (size_t)(j * 32) * KDIM + koff);
    };

    load_chunk(0); CP_COMMIT();
    load_chunk(1); CP_COMMIT();

    for (int n = 0; n < 36; n++) {
        if (n < 35) CP_WAIT1(); else CP_WAIT0();
        __syncthreads();

        const uint32_t st = sb + (uint32_t)(n % 3) * STAGE;
        const uint32_t abuf = st, bbuf = st + BOFF;
        const bool first = ((n & 3) == 0);

        #pragma unroll
        for (int ks = 0; ks < 4; ks++) {
            uint32_t af[2][4];
            #pragma unroll
            for (int mi = 0; mi < 2; mi++)
                LDSM_X4T(af[mi], abuf + SWZB((uint32_t)(
                    (ks * 16 + a_kr) * 256 + a_mc2 + mi * 32)));
            uint32_t bf[2][4];
            #pragma unroll
            for (int nb = 0; nb < 2; nb++)
                LDSM_X4(bf[nb], bbuf + SWZ128((uint32_t)(
                    (b_nr + nb * 16) * 128 + ks * 32 + b_kc)));
            #pragma unroll
            for (int mi = 0; mi < 2; mi++)
                #pragma unroll
                for (int ni = 0; ni < 4; ni++) {
                    const uint32_t* bp = &bf[ni >> 1][(ni & 1) * 2];
                    if (first && ks == 0) mma_z(acc[mi][ni], af[mi], bp);
                    else                  mma_a(acc[mi][ni], af[mi], bp);
                }
        }

        if (n + 2 < 36) { load_chunk(n + 2); CP_COMMIT(); }

        if ((n & 3) == 3) {   // group boundary (256 k): ADC + accumulate
            #pragma unroll
            for (int mi = 0; mi < 2; mi++)
                #pragma unroll
                for (int ni = 0; ni < 4; ni++)
                    #pragma unroll
                    for (int e = 0; e < 4; e++) {
                        float q2 = rintf(acc[mi][ni][e] * scaleQ);
                        q2 = fminf(fmaxf(q2, -128.f), 127.f);
                        tot[mi][ni][e] += q2;
                    }
        }
    }

    // ---- stage warp tile (32m x 32n) in smem, then coalesced global stores --
    __syncthreads();
    float* st = (float*)(gsm + wid * 4224);      // 32 x 33 floats
    #pragma unroll
    for (int mi = 0; mi < 2; mi++)
        #pragma unroll
        for (int ni = 0; ni < 4; ni++)
            #pragma unroll
            for (int e = 0; e < 4; e++) {
                int row = mi * 16 + (lane >> 2) + (e >> 1) * 8;
                int col = ni * 8 + (lane & 3) * 2 + (e & 1);
                st[row * 33 + col] = tot[mi][ni][e] * 0.001f;
            }
    __syncwarp();

    const int mg = m0 + wm * 32;
    const int bb = mg >> 10, l0 = mg & 1023;
    const size_t obase = ((size_t)(bb * 256 + n0 + wn * 32) << 10) + l0 + lane;
    #pragma unroll 8
    for (int o = 0; o < 32; o++)
        out[obase + ((size_t)o << 10)] = st[lane * 33 + o];
}

// ---------------------------------------------------------------------------
extern "C" void kernel_launch(void* const* d_in, const int* in_sizes, int n_in,
                              void* d_out, int out_size) {
    const float* x = (const float*)d_in[0];
    const float* w = (const float*)d_in[1];
    if (n_in >= 2 && in_sizes[0] == NW && in_sizes[1] == NX) {
        x = (const float*)d_in[1];
        w = (const float*)d_in[0];
    }
    float* out = (float*)d_out;

    int rem = (out_size > NOUT) ? (out_size - NOUT) : 0;
    int tb = (rem > 0) ? (rem + 255) / 256 : 1;
    init_tail_kernel<<<tb, 256>>>(out, NOUT, out_size);

    absmax_fused_kernel<<<1280, 256>>>(x, w);

    prep_fused_kernel<<<1152 + KDIM * 16, 256>>>(x, w);

    cudaFuncSetAttribute(hgemm_kernel,
                         cudaFuncAttributeMaxDynamicSharedMemorySize, SM_TOTAL);
    dim3 grid(OC / 64, MTOT / 128);   // 4 x 256
    hgemm_kernel<<<grid, 256, SM_TOTAL>>>(out);
}